// round 8
// baseline (speedup 1.0000x reference)
#include <cuda_runtime.h>

#define NB 4
#define NC 200
#define NG 32
#define NN 32256
#define CH 128                    // anchors per block
#define NBX (NN / CH)             // 252
#define TOTAL_BLOCKS (NB * NBX)   // 1008 -> single wave at 7 blocks/SM
#define QPT ((CH * 50) / 256)     // 25 quads per thread in phase B
#define LOG2E 1.4426950408889634f
#define LN2   0.69314718055994531f

__device__ double g_acc[3];
__device__ unsigned g_cnt;
__device__ unsigned g_done;

__device__ __forceinline__ float f_ex2(float x){ float r; asm("ex2.approx.ftz.f32 %0,%1;" : "=f"(r) : "f"(x)); return r; }
__device__ __forceinline__ float f_lg2(float x){ float r; asm("lg2.approx.ftz.f32 %0,%1;" : "=f"(r) : "f"(x)); return r; }
__device__ __forceinline__ float f_rcp(float x){ float r; asm("rcp.approx.ftz.f32 %0,%1;" : "=f"(r) : "f"(x)); return r; }

// MUFU path: lg2(1+e^x) * sigmoid(x)^2  (3 MUFU)
__device__ __forceinline__ float g0_mufu(float x) {
    float u = f_ex2(x * LOG2E);
    float s = 1.f + u;
    float r = f_rcp(s);
    float l = f_lg2(s);
    float w = u * r;
    return l * w * w;
}

// FMA/ALU path: same function, ZERO MUFU.
__device__ __forceinline__ float g0_poly(float x) {
    float y = x * LOG2E;
    // ---- u = 2^y : split y = n + fr, fr in [-0.5, 0.5] ----
    float t  = y + 12582912.f;                 // 1.5*2^23 round-to-nearest
    int   n  = __float_as_int(t) - 0x4B400000; // integer part
    float fr = y - (t - 12582912.f);
    // 2^fr: Taylor deg 5 in fr (rel err ~2.4e-6 at |fr|=0.5)
    float p = 1.3333558e-3f;
    p = fmaf(p, fr, 9.6181291e-3f);
    p = fmaf(p, fr, 5.5504109e-2f);
    p = fmaf(p, fr, 2.4022651e-1f);
    p = fmaf(p, fr, 6.9314718e-1f);
    p = fmaf(p, fr, 1.f);
    float u = __int_as_float(__float_as_int(p) + (n << 23));
    float s = 1.f + u;
    // ---- l = lg2(s) : centered mantissa m in [0.7071, 1.4142) ----
    int   i  = __float_as_int(s);
    int   j  = i - 0x3F3504F3;                 // bits of sqrt(0.5)
    int   ei = j >> 23;
    float m  = __int_as_float(i - (ei << 23));
    float z  = m - 1.f;                        // z in [-0.2929, 0.4142)
    // lg2(1+z) = z * (log2e * ln(1+z)/z), Taylor deg 9 (abs err ~2.2e-5)
    float q = 0.16029945f;
    q = fmaf(q, z, -0.18033688f);
    q = fmaf(q, z,  0.20609929f);
    q = fmaf(q, z, -0.24044917f);
    q = fmaf(q, z,  0.28853901f);
    q = fmaf(q, z, -0.36067376f);
    q = fmaf(q, z,  0.48089834f);
    q = fmaf(q, z, -0.72134752f);
    q = fmaf(q, z,  1.4426950f);
    float l = fmaf(z, q, (float)ei);
    // ---- r = 1/s : magic seed + 2 Newton (rel err ~1e-5) ----
    float r = __int_as_float(0x7EF311C3 - i);
    r = r * fmaf(-s, r, 2.f);
    r = r * fmaf(-s, r, 2.f);
    float w = u * r;
    return l * w * w;
}

__global__ void __launch_bounds__(256, 7)
loss_fused(const float* __restrict__ logits,        // [B,N,C]
           const float* __restrict__ psegs,         // [B,N,3]
           const float* __restrict__ grids,         // [B,N]
           const float* __restrict__ fps,           // [B]
           const float* __restrict__ gts,           // [B,G,2]
           const int*   __restrict__ glab,          // [B,G]
           const unsigned char* __restrict__ mask,  // [B,N]
           float* __restrict__ out)                 // [3]
{
    __shared__ unsigned s_tgt[CH * 8];   // 224-bit class-target mask per anchor
    __shared__ float    s_gv[CH], s_p1[CH], s_p2[CH], s_vv[CH];
    __shared__ float    s_red[3 * 8];
    __shared__ int      s_redc[8];

    const int tid  = threadIdx.x;
    const int lane = tid & 31;
    const int warp = tid >> 5;
    const int b    = blockIdx.y;
    const int n0   = blockIdx.x * CH;

    #pragma unroll
    for (int k = 0; k < 4; ++k) s_tgt[tid + k * 256] = 0u;
    // stage per-anchor scalars through smem (kills serial LDG latency in A)
    if (tid < CH) {
        long long bn = (long long)b * NN + n0 + tid;
        s_gv[tid] = grids[bn];
        s_p1[tid] = psegs[bn * 3 + 1];
        s_p2[tid] = psegs[bn * 3 + 2];
        s_vv[tid] = mask[bn] ? 0.f : 1.f;
    }
    __syncthreads();

    // ---------------- Phase A: matching + seg/IoU + target masks ----------
    float2 seg  = ((const float2*)gts)[b * NG + lane];
    float s_g   = seg.x, e_g = seg.y;
    float len_g = e_g - s_g;
    int   lbl   = glab[b * NG + lane];
    float Cm    = 3.0f * fps[b] * 1.41421356237309515f;  // 3*fps*sqrt(2)

    int lvl = (n0 >= 16384) + (n0 >= 24576) + (n0 >= 28672) + (n0 >= 30720) + (n0 >= 31744);
    float lo = (lvl == 0) ? 0.f : Cm * (float)(1 << (lvl - 1));
    float hi = (lvl == 5) ? __int_as_float(0x7f800000) : Cm * (float)(1 << lvl);
    bool inb = (len_g >= lo) && (len_g < hi);

    float ce_acc = 0.f, seg_acc = 0.f, iou_acc = 0.f;
    int cnt = 0;

    #pragma unroll 4
    for (int i = 0; i < CH / 8; ++i) {   // 16 anchors per warp
        int a = warp * (CH / 8) + i;
        float gv = s_gv[a];
        bool pos = inb && (gv > s_g) && (gv < e_g);
        if (pos) {
            cnt++;
            float ps1 = s_p1[a], ps2 = s_p2[a];
            float d1 = ps1 - __logf(gv - s_g);
            float d2 = ps2 - __logf(e_g - gv);
            float a1 = fabsf(d1), a2 = fabsf(d2);
            seg_acc += (a1 < 1.f ? 0.5f * d1 * d1 : a1 - 0.5f)
                     + (a2 < 1.f ? 0.5f * d2 * d2 : a2 - 0.5f);
            float pls = gv - __expf(ps1);
            float ple = gv + __expf(ps2);
            float inter = fmaxf(fminf(ple, e_g) - fmaxf(pls, s_g), 0.f);
            float uni   = (ple - pls) + len_g - inter;
            iou_acc += 1.f - __fdividef(inter, uni);
            atomicOr(&s_tgt[a * 8 + (lbl >> 5)], 1u << (lbl & 31));
        }
    }
    // NOTE: no barrier here — phase B reads no phase-A shared state.

    // ---------------- Phase B: t=0 focal stream, pipe-split ----------------
    // Per quad: 2 elements via MUFU path, 2 via FMA/ALU poly path.
    const float4* basep = (const float4*)(logits + ((size_t)b * NN + n0) * NC);
    float c0 = 0.f, c1 = 0.f, c2 = 0.f, c3 = 0.f;
    #pragma unroll 5
    for (int k = 0; k < QPT; ++k) {
        float4 v = basep[tid + k * 256];
        c0 += g0_mufu(v.x);
        c1 += g0_poly(v.y);
        c2 += g0_mufu(v.z);
        c3 += g0_poly(v.w);
    }
    ce_acc += (c0 + c1) + (c2 + c3);
    __syncthreads();   // s_tgt / s_vv complete before phase C

    // ---------------- Phase C: corrections ---------------------------------
    const float* rowbase = logits + ((size_t)b * NN + n0) * NC;

    // (1) invalid anchors: subtract their whole-row t=0 contribution (rare).
    for (int a = warp; a < CH; a += 8) {
        if (s_vv[a] == 0.f) {
            const float* rp = rowbase + a * NC;
            float sub = 0.f;
            for (int c = lane; c < NC; c += 32) sub += g0_mufu(rp[c]);
            #pragma unroll
            for (int o = 16; o; o >>= 1) sub += __shfl_xor_sync(0xffffffffu, sub, o);
            if (lane == 0) ce_acc -= sub;
        }
    }

    // (2) sparse t=1 cells: add (fl1 - fl0) in lg2 units:
    //     (1/3)*(l - x*log2e)*r^2 - l*w^2   (times valid)
    #pragma unroll
    for (int kk = 0; kk < 4; ++kk) {
        int wq = tid + kk * 256;
        unsigned m = s_tgt[wq];
        if (m) {
            int a  = wq >> 3;
            int wi = wq & 7;
            float vf = s_vv[a];
            const float* rp = rowbase + a * NC + wi * 32;
            do {
                int bp = __ffs(m) - 1; m &= m - 1;
                float x = rp[bp];
                float t = x * LOG2E;
                float u = f_ex2(t);
                float s = 1.f + u;
                float r = f_rcp(s);
                float l = f_lg2(s);
                float w = u * r;
                ce_acc += vf * (0.33333333333f * (l - t) * r * r - l * w * w);
            } while (m);
        }
    }

    // ---------------- Reduction + last-block finalize ----------------------
    #pragma unroll
    for (int o = 16; o; o >>= 1) {
        ce_acc  += __shfl_xor_sync(0xffffffffu, ce_acc,  o);
        seg_acc += __shfl_xor_sync(0xffffffffu, seg_acc, o);
        iou_acc += __shfl_xor_sync(0xffffffffu, iou_acc, o);
        cnt     += __shfl_xor_sync(0xffffffffu, cnt,     o);
    }
    if (lane == 0) {
        s_red[warp]      = ce_acc;
        s_red[8 + warp]  = seg_acc;
        s_red[16 + warp] = iou_acc;
        s_redc[warp]     = cnt;
    }
    __syncthreads();
    if (tid == 0) {
        double ce = 0.0, sg = 0.0, io = 0.0; int c = 0;
        #pragma unroll
        for (int w = 0; w < 8; ++w) {
            ce += (double)s_red[w];
            sg += (double)s_red[8 + w];
            io += (double)s_red[16 + w];
            c  += s_redc[w];
        }
        atomicAdd(&g_acc[0], ce);
        atomicAdd(&g_acc[1], sg);
        atomicAdd(&g_acc[2], io);
        atomicAdd(&g_cnt, (unsigned)c);
        __threadfence();
        unsigned t = atomicAdd(&g_done, 1u);
        if (t == TOTAL_BLOCKS - 1) {
            double np = (double)atomicAdd(&g_cnt, 0u);
            if (np < 1.0) np = 1.0;
            double a0 = atomicAdd(&g_acc[0], 0.0);
            double a1 = atomicAdd(&g_acc[1], 0.0);
            double a2 = atomicAdd(&g_acc[2], 0.0);
            out[0] = (float)(a0 * (0.75 * (double)LN2) / np);  // deferred 0.75*ln2
            out[1] = (float)(a1 / np);
            out[2] = (float)(a2 / np);
            g_acc[0] = 0.0; g_acc[1] = 0.0; g_acc[2] = 0.0;
            g_cnt = 0u; g_done = 0u;
        }
    }
}

extern "C" void kernel_launch(void* const* d_in, const int* in_sizes, int n_in,
                              void* d_out, int out_size) {
    const float*         logits = (const float*)d_in[0];
    const float*         psegs  = (const float*)d_in[1];
    const float*         grids  = (const float*)d_in[2];
    const float*         fps    = (const float*)d_in[3];
    const float*         gts    = (const float*)d_in[4];
    const int*           glab   = (const int*)d_in[5];
    const unsigned char* maskp  = (const unsigned char*)d_in[6];
    float* out = (float*)d_out;

    dim3 grid(NBX, NB);
    loss_fused<<<grid, 256>>>(logits, psegs, grids, fps, gts, glab, maskp, out);
    (void)in_sizes; (void)n_in; (void)out_size;
}

// round 9
// speedup vs baseline: 1.3139x; 1.3139x over previous
#include <cuda_runtime.h>

#define NB 4
#define NC 200
#define NG 32
#define NN 32256
#define CH 128                    // anchors per block
#define NBX (NN / CH)             // 252
#define TOTAL_BLOCKS (NB * NBX)   // 1008 -> single wave
#define QPT ((CH * 50) / 256)     // 25 quads per thread in phase B
#define LOG2E 1.4426950408889634f
#define LN2   0.69314718055994531f

__device__ double g_acc[3];
__device__ unsigned g_cnt;
__device__ unsigned g_done;

__device__ __forceinline__ float f_ex2(float x){ float r; asm("ex2.approx.ftz.f32 %0,%1;" : "=f"(r) : "f"(x)); return r; }
__device__ __forceinline__ float f_lg2(float x){ float r; asm("lg2.approx.ftz.f32 %0,%1;" : "=f"(r) : "f"(x)); return r; }
__device__ __forceinline__ float f_rcp(float x){ float r; asm("rcp.approx.ftz.f32 %0,%1;" : "=f"(r) : "f"(x)); return r; }

// 2-MUFU focal core: lg2(1+e^x) * sigmoid(x)^2.
// ex2 + lg2 on MUFU; reciprocal via bit-magic seed + 2 Newton (FMA pipe).
__device__ __forceinline__ float g0_2m(float x) {
    float t = x * LOG2E;
    float u = f_ex2(t);                    // MUFU #1
    float s = 1.f + u;
    float l = f_lg2(s);                    // MUFU #2
    float r = __int_as_float(0x7EF311C3 - __float_as_int(s));  // |rel err| <~5%
    r = r * fmaf(-s, r, 2.f);              // Newton 1
    r = r * fmaf(-s, r, 2.f);              // Newton 2  (rel err ~6e-6)
    float w = u * r;                       // sigmoid(x)
    return l * w * w;
}

__global__ void __launch_bounds__(256, 7)
loss_fused(const float* __restrict__ logits,        // [B,N,C]
           const float* __restrict__ psegs,         // [B,N,3]
           const float* __restrict__ grids,         // [B,N]
           const float* __restrict__ fps,           // [B]
           const float* __restrict__ gts,           // [B,G,2]
           const int*   __restrict__ glab,          // [B,G]
           const unsigned char* __restrict__ mask,  // [B,N]
           float* __restrict__ out)                 // [3]
{
    __shared__ unsigned s_tgt[CH * 8];   // 224-bit class-target mask per anchor
    __shared__ float    s_gv[CH], s_p1[CH], s_p2[CH], s_vv[CH];
    __shared__ float    s_red[3 * 8];
    __shared__ int      s_redc[8];

    const int tid  = threadIdx.x;
    const int lane = tid & 31;
    const int warp = tid >> 5;
    const int b    = blockIdx.y;
    const int n0   = blockIdx.x * CH;

    #pragma unroll
    for (int k = 0; k < 4; ++k) s_tgt[tid + k * 256] = 0u;
    // stage per-anchor scalars through smem
    if (tid < CH) {
        long long bn = (long long)b * NN + n0 + tid;
        s_gv[tid] = grids[bn];
        s_p1[tid] = psegs[bn * 3 + 1];
        s_p2[tid] = psegs[bn * 3 + 2];
        s_vv[tid] = mask[bn] ? 0.f : 1.f;
    }
    __syncthreads();

    // ---------------- Phase A: matching + seg/IoU + target masks ----------
    float2 seg  = ((const float2*)gts)[b * NG + lane];
    float s_g   = seg.x, e_g = seg.y;
    float len_g = e_g - s_g;
    int   lbl   = glab[b * NG + lane];
    float Cm    = 3.0f * fps[b] * 1.41421356237309515f;  // 3*fps*sqrt(2)

    int lvl = (n0 >= 16384) + (n0 >= 24576) + (n0 >= 28672) + (n0 >= 30720) + (n0 >= 31744);
    float lo = (lvl == 0) ? 0.f : Cm * (float)(1 << (lvl - 1));
    float hi = (lvl == 5) ? __int_as_float(0x7f800000) : Cm * (float)(1 << lvl);
    bool inb = (len_g >= lo) && (len_g < hi);

    float ce_acc = 0.f, seg_acc = 0.f, iou_acc = 0.f;
    int cnt = 0;

    #pragma unroll 4
    for (int i = 0; i < CH / 8; ++i) {   // 16 anchors per warp
        int a = warp * (CH / 8) + i;
        float gv = s_gv[a];
        bool pos = inb && (gv > s_g) && (gv < e_g);
        if (pos) {
            cnt++;
            float ps1 = s_p1[a], ps2 = s_p2[a];
            float d1 = ps1 - __logf(gv - s_g);
            float d2 = ps2 - __logf(e_g - gv);
            float a1 = fabsf(d1), a2 = fabsf(d2);
            seg_acc += (a1 < 1.f ? 0.5f * d1 * d1 : a1 - 0.5f)
                     + (a2 < 1.f ? 0.5f * d2 * d2 : a2 - 0.5f);
            float pls = gv - __expf(ps1);
            float ple = gv + __expf(ps2);
            float inter = fmaxf(fminf(ple, e_g) - fmaxf(pls, s_g), 0.f);
            float uni   = (ple - pls) + len_g - inter;
            iou_acc += 1.f - __fdividef(inter, uni);
            atomicOr(&s_tgt[a * 8 + (lbl >> 5)], 1u << (lbl & 31));
        }
    }
    // no barrier: phase B reads no phase-A shared state

    // ---------------- Phase B: homogeneous 2-MUFU focal stream -------------
    const float4* basep = (const float4*)(logits + ((size_t)b * NN + n0) * NC);
    float c0 = 0.f, c1 = 0.f, c2 = 0.f, c3 = 0.f;
    #pragma unroll
    for (int k = 0; k < QPT; ++k) {
        float4 v = basep[tid + k * 256];
        c0 += g0_2m(v.x);
        c1 += g0_2m(v.y);
        c2 += g0_2m(v.z);
        c3 += g0_2m(v.w);
    }
    ce_acc += (c0 + c1) + (c2 + c3);
    __syncthreads();   // s_tgt / s_vv complete before phase C

    // ---------------- Phase C: corrections ---------------------------------
    const float* rowbase = logits + ((size_t)b * NN + n0) * NC;

    // (1) invalid anchors: subtract whole-row t=0 contribution (rare path).
    for (int a = warp; a < CH; a += 8) {
        if (s_vv[a] == 0.f) {
            const float* rp = rowbase + a * NC;
            float sub = 0.f;
            for (int c = lane; c < NC; c += 32) sub += g0_2m(rp[c]);
            #pragma unroll
            for (int o = 16; o; o >>= 1) sub += __shfl_xor_sync(0xffffffffu, sub, o);
            if (lane == 0) ce_acc -= sub;
        }
    }

    // (2) sparse t=1 cells: add (fl1 - fl0) in lg2 units:
    //     (1/3)*(l - x*log2e)*r^2 - l*w^2   (times valid)
    #pragma unroll
    for (int kk = 0; kk < 4; ++kk) {
        int wq = tid + kk * 256;
        unsigned m = s_tgt[wq];
        if (m) {
            int a  = wq >> 3;
            int wi = wq & 7;
            float vf = s_vv[a];
            const float* rp = rowbase + a * NC + wi * 32;
            do {
                int bp = __ffs(m) - 1; m &= m - 1;
                float x = rp[bp];
                float t = x * LOG2E;
                float u = f_ex2(t);
                float s = 1.f + u;
                float r = f_rcp(s);
                float l = f_lg2(s);
                float w = u * r;
                ce_acc += vf * (0.33333333333f * (l - t) * r * r - l * w * w);
            } while (m);
        }
    }

    // ---------------- Reduction + last-block finalize ----------------------
    #pragma unroll
    for (int o = 16; o; o >>= 1) {
        ce_acc  += __shfl_xor_sync(0xffffffffu, ce_acc,  o);
        seg_acc += __shfl_xor_sync(0xffffffffu, seg_acc, o);
        iou_acc += __shfl_xor_sync(0xffffffffu, iou_acc, o);
        cnt     += __shfl_xor_sync(0xffffffffu, cnt,     o);
    }
    if (lane == 0) {
        s_red[warp]      = ce_acc;
        s_red[8 + warp]  = seg_acc;
        s_red[16 + warp] = iou_acc;
        s_redc[warp]     = cnt;
    }
    __syncthreads();
    if (tid == 0) {
        double ce = 0.0, sg = 0.0, io = 0.0; int c = 0;
        #pragma unroll
        for (int w = 0; w < 8; ++w) {
            ce += (double)s_red[w];
            sg += (double)s_red[8 + w];
            io += (double)s_red[16 + w];
            c  += s_redc[w];
        }
        atomicAdd(&g_acc[0], ce);
        atomicAdd(&g_acc[1], sg);
        atomicAdd(&g_acc[2], io);
        atomicAdd(&g_cnt, (unsigned)c);
        __threadfence();
        unsigned t = atomicAdd(&g_done, 1u);
        if (t == TOTAL_BLOCKS - 1) {
            double np = (double)atomicAdd(&g_cnt, 0u);
            if (np < 1.0) np = 1.0;
            double a0 = atomicAdd(&g_acc[0], 0.0);
            double a1 = atomicAdd(&g_acc[1], 0.0);
            double a2 = atomicAdd(&g_acc[2], 0.0);
            out[0] = (float)(a0 * (0.75 * (double)LN2) / np);  // deferred 0.75*ln2
            out[1] = (float)(a1 / np);
            out[2] = (float)(a2 / np);
            g_acc[0] = 0.0; g_acc[1] = 0.0; g_acc[2] = 0.0;
            g_cnt = 0u; g_done = 0u;
        }
    }
}

extern "C" void kernel_launch(void* const* d_in, const int* in_sizes, int n_in,
                              void* d_out, int out_size) {
    const float*         logits = (const float*)d_in[0];
    const float*         psegs  = (const float*)d_in[1];
    const float*         grids  = (const float*)d_in[2];
    const float*         fps    = (const float*)d_in[3];
    const float*         gts    = (const float*)d_in[4];
    const int*           glab   = (const int*)d_in[5];
    const unsigned char* maskp  = (const unsigned char*)d_in[6];
    float* out = (float*)d_out;

    dim3 grid(NBX, NB);
    loss_fused<<<grid, 256>>>(logits, psegs, grids, fps, gts, glab, maskp, out);
    (void)in_sizes; (void)n_in; (void)out_size;
}